// round 4
// baseline (speedup 1.0000x reference)
#include <cuda_runtime.h>

// logLikelihood_loss: sum over (B,T,P) of -log(clip(bivariate_gaussian_pdf, 1e-10)) / P
// B=64, T=128, P=512 -> 4,194,304 elements. y_target: (...,3), o_pred: (...,5).
// Pure streaming reduction -> HBM-bound. Log-domain formulation avoids exp/log round-trip.

#define N_ELEM   4194304
#define GROUPS   (N_ELEM / 4)      // 4 elements per thread
#define THREADS  256
#define BLOCKS   (GROUPS / THREADS) // 4096

__global__ void zero_out_kernel(float* __restrict__ out) {
    if (threadIdx.x == 0 && blockIdx.x == 0) out[0] = 0.0f;
}

// Accurate-enough tanh built from fast exp (independent of -use_fast_math mapping
// of tanhf to tanh.approx, whose abs error would poison 1-rho^2).
__device__ __forceinline__ float fast_tanh(float x) {
    float ax = fabsf(x);
    float e  = __expf(2.0f * ax);                 // 2|x| <= ~11 for these inputs
    float t  = 1.0f - __fdividef(2.0f, e + 1.0f); // in [0,1)
    return copysignf(t, x);
}

__global__ __launch_bounds__(THREADS)
void nll_kernel(const float* __restrict__ y, const float* __restrict__ o,
                float* __restrict__ out) {
    const int g = blockIdx.x * blockDim.x + threadIdx.x;   // group of 4 elements

    // Vectorized loads: 5 float4 from o_pred (20 floats = 4 elems x 5),
    //                   3 float4 from y_target (12 floats = 4 elems x 3).
    const float4* o4 = reinterpret_cast<const float4*>(o) + (size_t)g * 5;
    const float4* y4 = reinterpret_cast<const float4*>(y) + (size_t)g * 3;

    float of[20];
    float yf[12];
#pragma unroll
    for (int k = 0; k < 5; k++) reinterpret_cast<float4*>(of)[k] = o4[k];
#pragma unroll
    for (int k = 0; k < 3; k++) reinterpret_cast<float4*>(yf)[k] = y4[k];

    const float LOG_2PI  = 1.8378770664093453f;   // ln(2*pi)
    const float CLAMP_HI = 23.025850929940457f;   // -ln(1e-10)

    float acc = 0.0f;
#pragma unroll
    for (int j = 0; j < 4; j++) {
        float mux = of[5 * j + 0];
        float muy = of[5 * j + 1];
        float lsx = of[5 * j + 2];   // log(sx)
        float lsy = of[5 * j + 3];   // log(sy)
        float cra = of[5 * j + 4];   // pre-tanh corr

        float y1 = yf[3 * j + 1];
        float y2 = yf[3 * j + 2];

        float inv_sx = __expf(-lsx);
        float inv_sy = __expf(-lsy);
        float nx = (y1 - mux) * inv_sx;
        float ny = (y2 - muy) * inv_sy;

        float t  = fast_tanh(cra);
        float om = fmaf(-t, t, 1.0f);             // 1 - rho^2 > 0
        float z  = fmaf(nx, nx, fmaf(ny, ny, -2.0f * t * nx * ny)); // >= 0

        // -log pdf = z/(2*om) + log(2pi) + log(sx) + log(sy) + 0.5*log(om)
        float nll = 0.5f * __fdividef(z, om)
                  + (LOG_2PI + lsx + lsy + 0.5f * __logf(om));
        acc += fminf(nll, CLAMP_HI);              // == -log(clip(pdf, 1e-10))
    }

    // Warp reduction
#pragma unroll
    for (int off = 16; off; off >>= 1)
        acc += __shfl_down_sync(0xffffffffu, acc, off);

    __shared__ float wsum[THREADS / 32];
    const int lane = threadIdx.x & 31;
    const int wid  = threadIdx.x >> 5;
    if (lane == 0) wsum[wid] = acc;
    __syncthreads();

    if (wid == 0) {
        float v = (lane < THREADS / 32) ? wsum[lane] : 0.0f;
#pragma unroll
        for (int off = 4; off; off >>= 1)
            v += __shfl_down_sync(0xffffffffu, v, off);
        if (lane == 0)
            atomicAdd(out, v * (1.0f / 512.0f));  // divide by P once per block
    }
}

extern "C" void kernel_launch(void* const* d_in, const int* in_sizes, int n_in,
                              void* d_out, int out_size) {
    const float* y = (const float*)d_in[0];   // y_target, 12,582,912 floats
    const float* o = (const float*)d_in[1];   // o_pred,  20,971,520 floats
    float* out = (float*)d_out;               // scalar fp32

    zero_out_kernel<<<1, 32>>>(out);
    nll_kernel<<<BLOCKS, THREADS>>>(y, o, out);
}